// round 5
// baseline (speedup 1.0000x reference)
#include <cuda_runtime.h>

#define BB 4
#define ROI 90
#define TT 200
#define HH 3
#define FF 96
#define G3 288
#define NB 12   // BB*HH

typedef unsigned long long u64;

// scratch (device globals; no runtime alloc allowed)
__device__ float g_act[(size_t)NB * ROI * TT * FF];        // (n, roi, t, f)
__device__ float g_xp [(size_t)ROI * TT * NB * G3];        // (roi, t, n, g)

__device__ __forceinline__ u64 pk2(float lo, float hi) {
    u64 r; asm("mov.b64 %0,{%1,%2};" : "=l"(r) : "f"(lo), "f"(hi)); return r;
}
__device__ __forceinline__ void fma2(u64& d, u64 a, u64 b) {
    asm("fma.rn.f32x2 %0,%1,%2,%3;" : "=l"(d) : "l"(a), "l"(b), "l"(d));
}
__device__ __forceinline__ float red2(u64 v) {
    float lo, hi; asm("mov.b64 {%0,%1},%2;" : "=f"(lo), "=f"(hi) : "l"(v));
    return lo + hi;
}
__device__ __forceinline__ float sigmoidf_fast(float x) {
    return __fdividef(1.0f, 1.0f + __expf(-x));
}
__device__ __forceinline__ float tanhf_fast(float x) {
    float e = __expf(2.0f * x);
    return 1.0f - __fdividef(2.0f, e + 1.0f);
}

// ---------------------------------------------------------------------------
// K1: per-(b,t,h, row-half) block: sparse agg + MLP1(bn,elu) + MLP2(bn,relu)
// ---------------------------------------------------------------------------
__global__ __launch_bounds__(288, 2) void k1_agg_mlp(
    const float* __restrict__ x, const float* __restrict__ a,
    const float* __restrict__ eps,
    const float* __restrict__ W1, const float* __restrict__ b1,
    const float* __restrict__ g1, const float* __restrict__ be1,
    const float* __restrict__ W2, const float* __restrict__ b2,
    const float* __restrict__ g2, const float* __restrict__ be2)
{
    extern __shared__ float sm[];
    float* xs  = sm;              // 8640 floats: full x tile; later h1 (45x96)
    float* buf = sm + 8640;       // 4320 floats: agg rows (45x96)
    unsigned char* idx8 = (unsigned char*)(sm + 8640 + 4320);  // 45*96 bytes
    int* cnts = (int*)(idx8 + 45 * 96);                        // 45 ints

    const int bid = blockIdx.x;
    const int half = blockIdx.y;
    const int b   = bid / (TT * HH);
    const int rem = bid % (TT * HH);
    const int t   = rem / HH;
    const int hh  = rem % HH;
    const int tid = threadIdx.x;

    {
        const float4* xsrc = (const float4*)x;
        for (int idx = tid; idx < ROI * 24; idx += 288) {
            int i = idx / 24, c4 = idx % 24;
            ((float4*)xs)[i * 24 + c4] =
                xsrc[(((((size_t)b * ROI + i) * TT + t) * HH + hh) * FF) / 4 + c4];
        }
    }

    const int warp = tid >> 5, lane = tid & 31;
    for (int r = warp; r < 45; r += 9) {
        int i = half * 45 + r;
        size_t aoff = ((((size_t)b * ROI + i) * TT + t) * HH + hh) * ROI;
        int cnt = 0;
        #pragma unroll
        for (int c0 = 0; c0 < 96; c0 += 32) {
            int j = c0 + lane;
            float v = (j < ROI) ? a[aoff + j] : 0.0f;
            unsigned m = __ballot_sync(0xffffffffu, v != 0.0f);
            if (v != 0.0f) {
                int pos = cnt + __popc(m & ((1u << lane) - 1u));
                idx8[r * 96 + pos] = (unsigned char)j;
            }
            cnt += __popc(m);
        }
        if (lane == 0) cnts[r] = cnt;
    }
    __syncthreads();

    const float epsv = eps[0];

    {
        const int c4 = tid % 24;
        const int ig = tid / 24;
        for (int r = ig; r < 45; r += 12) {
            int i = half * 45 + r;
            float4 base = ((const float4*)xs)[i * 24 + c4];
            float4 s = make_float4(epsv * base.x, epsv * base.y,
                                   epsv * base.z, epsv * base.w);
            int cnt = cnts[r];
            const unsigned char* il = idx8 + r * 96;
            for (int s0 = 0; s0 < cnt; s0++) {
                int j = il[s0];
                float4 v = ((const float4*)xs)[j * 24 + c4];
                s.x += v.x; s.y += v.y; s.z += v.z; s.w += v.w;
            }
            ((float4*)buf)[r * 24 + c4] = s;
        }
    }
    __syncthreads();

    const int c  = tid % 96;
    const int ib = tid / 96;

    // GEMM1
    {
        u64 acc[15];
        #pragma unroll
        for (int r = 0; r < 15; r++) acc[r] = 0ull;
        for (int k = 0; k < 96; k += 4) {
            float wa = __ldg(&W1[(k + 0) * 96 + c]);
            float wb = __ldg(&W1[(k + 1) * 96 + c]);
            float wc = __ldg(&W1[(k + 2) * 96 + c]);
            float wd = __ldg(&W1[(k + 3) * 96 + c]);
            u64 w01 = pk2(wa, wb), w23 = pk2(wc, wd);
            #pragma unroll
            for (int r = 0; r < 15; r++) {
                ulonglong2 av = *(const ulonglong2*)&buf[(ib + 3 * r) * 96 + k];
                fma2(acc[r], av.x, w01);
                fma2(acc[r], av.y, w23);
            }
        }
        float gs  = g1[c] * rsqrtf(1.0f + 1e-5f);
        float bbv = be1[c];
        float b1c = b1[c];
        __syncthreads();
        #pragma unroll
        for (int r = 0; r < 15; r++) {
            int rr = ib + 3 * r;
            float y = (red2(acc[r]) + b1c) * gs + bbv;
            y = (y > 0.0f) ? y : (__expf(y) - 1.0f);
            xs[rr * 96 + c] = y;
        }
    }
    __syncthreads();

    // GEMM2
    {
        u64 acc[15];
        #pragma unroll
        for (int r = 0; r < 15; r++) acc[r] = 0ull;
        for (int k = 0; k < 96; k += 4) {
            float wa = __ldg(&W2[(k + 0) * 96 + c]);
            float wb = __ldg(&W2[(k + 1) * 96 + c]);
            float wc = __ldg(&W2[(k + 2) * 96 + c]);
            float wd = __ldg(&W2[(k + 3) * 96 + c]);
            u64 w01 = pk2(wa, wb), w23 = pk2(wc, wd);
            #pragma unroll
            for (int r = 0; r < 15; r++) {
                ulonglong2 av = *(const ulonglong2*)&xs[(ib + 3 * r) * 96 + k];
                fma2(acc[r], av.x, w01);
                fma2(acc[r], av.y, w23);
            }
        }
        float gs  = g2[c] * rsqrtf(1.0f + 1e-5f);
        float bbv = be2[c];
        float b2c = b2[c];
        const int n = b * HH + hh;
        #pragma unroll
        for (int r = 0; r < 15; r++) {
            int i = half * 45 + ib + 3 * r;
            float y = (red2(acc[r]) + b2c) * gs + bbv;
            y = fmaxf(y, 0.0f);
            g_act[(((size_t)n * ROI + i) * TT + t) * FF + c] = y;
        }
    }
}

// ---------------------------------------------------------------------------
// K2: GRU input projection. grid (50, 90): t-tile 4 -> 48 rows x 288 g x 96 k
//     576 threads: (g, row-half). Weights staged in smem, k-chunked.
// ---------------------------------------------------------------------------
#define WPAD 36   // padded chunk row stride (32 k-floats + 4 pad)

__global__ __launch_bounds__(576, 1) void k2_proj(
    const float* __restrict__ Wih, const float* __restrict__ bih)
{
    extern __shared__ float sm[];
    float* acts = sm;                  // 48*96 = 4608 floats
    float* wsm  = sm + 4608;           // 288*36 = 10368 floats

    const int roi = blockIdx.y;
    const int t0  = blockIdx.x * 4;
    const int tid = threadIdx.x;
    const int g   = tid % G3;
    const int rh  = tid / G3;          // 0/1 -> rows [0,24) or [24,48)

    {
        const float4* src = (const float4*)g_act;
        #pragma unroll
        for (int it = 0; it < 2; it++) {
            int idx = it * 576 + tid;          // 48*24 = 1152 float4
            int r = idx / 24, c4 = idx % 24;
            int dt = r / NB, n = r % NB;
            ((float4*)acts)[idx] =
                src[((((size_t)n * ROI + roi) * TT + (t0 + dt)) * FF) / 4 + c4];
        }
    }

    u64 acc[24];
    #pragma unroll
    for (int r = 0; r < 24; r++) acc[r] = 0ull;

    const float* wbase = Wih + (size_t)roi * G3 * 96;

    #pragma unroll
    for (int c0 = 0; c0 < 96; c0 += 32) {
        __syncthreads();   // previous chunk consumed (covers acts on first pass)
        #pragma unroll
        for (int it = 0; it < 4; it++) {
            int idx = it * 576 + tid;          // 288*8 = 2304 float4
            int gg  = idx >> 3;
            int q   = idx & 7;
            float4 w = __ldg((const float4*)(wbase + gg * 96 + c0 + 4 * q));
            *(float4*)&wsm[gg * WPAD + 4 * q] = w;
        }
        __syncthreads();

        const float* wrow = &wsm[g * WPAD];
        #pragma unroll
        for (int kk4 = 0; kk4 < 8; kk4++) {
            ulonglong2 w = *(const ulonglong2*)&wrow[4 * kk4];
            #pragma unroll
            for (int rr = 0; rr < 24; rr++) {
                ulonglong2 av =
                    *(const ulonglong2*)&acts[(rh * 24 + rr) * 96 + c0 + 4 * kk4];
                fma2(acc[rr], av.x, w.x);
                fma2(acc[rr], av.y, w.y);
            }
        }
    }

    const float bv = __ldg(&bih[roi * G3 + g]);
    #pragma unroll
    for (int rr = 0; rr < 24; rr++) {
        int r = rh * 24 + rr;
        int dt = r / NB, n = r % NB;
        g_xp[(((size_t)roi * TT + (t0 + dt)) * NB + n) * G3 + g] = red2(acc[rr]) + bv;
    }
}

// ---------------------------------------------------------------------------
// K3: GRU recurrence. grid (90, 12): one block per (roi, sequence).
//     288 threads = one per gate row; FULL Whh row (96 floats = 48 u64) in
//     registers; h-state (96 floats) in smem; 200 steps, 2 barriers/step.
// ---------------------------------------------------------------------------
__global__ __launch_bounds__(288, 1) void k3_gru(
    const float* __restrict__ Whh, const float* __restrict__ bhh,
    float* __restrict__ out)
{
    __shared__ __align__(16) float hbuf[96];
    __shared__ __align__(16) float rbuf[96];
    __shared__ __align__(16) float zbuf[96];

    const int roi = blockIdx.x;
    const int n   = blockIdx.y;
    const int g   = threadIdx.x;

    u64 wr2[48];
    {
        const ulonglong2* wsrc = (const ulonglong2*)(Whh + ((size_t)roi * G3 + g) * 96);
        #pragma unroll
        for (int kk = 0; kk < 24; kk++) {
            ulonglong2 w = __ldg(&wsrc[kk]);
            wr2[2 * kk + 0] = w.x;
            wr2[2 * kk + 1] = w.y;
        }
    }
    const float bv = __ldg(&bhh[roi * G3 + g]);

    if (g < 96) hbuf[g] = 0.0f;
    __syncthreads();

    const int gtype = g / 96;   // 0:r  1:z  2:n
    const int j     = g % 96;
    const int bb    = n / HH, hh = n % HH;
    float* outb = out + ((((size_t)bb * ROI + roi) * TT) * HH + hh) * 96 + j;
    const float* xpb = g_xp + (((size_t)roi * TT) * NB + n) * G3 + g;

    for (int t = 0; t < TT; t++) {
        float xv = __ldg(&xpb[(size_t)t * NB * G3]);

        // hp = h . Whh[g] + bhh[g]  (two independent chains over full 96 k)
        u64 a2 = 0ull, b2 = 0ull;
        const ulonglong2* hrow = (const ulonglong2*)hbuf;
        #pragma unroll
        for (int kk = 0; kk < 24; kk++) {
            ulonglong2 hv = hrow[kk];
            fma2(a2, hv.x, wr2[2 * kk + 0]);
            fma2(b2, hv.y, wr2[2 * kk + 1]);
        }
        float hp = red2(a2) + red2(b2) + bv;

        if (gtype == 0)      rbuf[j] = sigmoidf_fast(xv + hp);
        else if (gtype == 1) zbuf[j] = sigmoidf_fast(xv + hp);
        __syncthreads();

        if (gtype == 2) {
            float r  = rbuf[j];
            float z  = zbuf[j];
            float hn = tanhf_fast(xv + r * hp);
            float h2 = (1.0f - z) * hn + z * hbuf[j];
            hbuf[j] = h2;
            outb[(size_t)t * HH * 96] = h2;
        }
        __syncthreads();
    }
}

// ---------------------------------------------------------------------------
extern "C" void kernel_launch(void* const* d_in, const int* in_sizes, int n_in,
                              void* d_out, int out_size)
{
    const float* x   = (const float*)d_in[0];
    const float* a   = (const float*)d_in[1];
    const float* eps = (const float*)d_in[2];
    const float* W1  = (const float*)d_in[3];
    const float* b1  = (const float*)d_in[4];
    const float* g1  = (const float*)d_in[5];
    const float* be1 = (const float*)d_in[6];
    const float* W2  = (const float*)d_in[7];
    const float* b2  = (const float*)d_in[8];
    const float* g2  = (const float*)d_in[9];
    const float* be2 = (const float*)d_in[10];
    const float* Wih = (const float*)d_in[11];
    const float* Whh = (const float*)d_in[12];
    const float* bih = (const float*)d_in[13];
    const float* bhh = (const float*)d_in[14];
    float* out = (float*)d_out;

    const int smem1 = (8640 + 4320) * 4 + 45 * 96 + 45 * 4;   // 56,340 B
    cudaFuncSetAttribute(k1_agg_mlp, cudaFuncAttributeMaxDynamicSharedMemorySize, smem1);

    const int smem2 = (4608 + 288 * WPAD) * 4;                // 59,904 B
    cudaFuncSetAttribute(k2_proj, cudaFuncAttributeMaxDynamicSharedMemorySize, smem2);

    k1_agg_mlp<<<dim3(BB * TT * HH, 2), 288, smem1>>>(x, a, eps, W1, b1, g1, be1,
                                                      W2, b2, g2, be2);
    k2_proj<<<dim3(TT / 4, ROI), 576, smem2>>>(Wih, bih);
    k3_gru<<<dim3(ROI, NB), 288>>>(Whh, bhh, out);
}

// round 6
// speedup vs baseline: 1.1627x; 1.1627x over previous
#include <cuda_runtime.h>

#define BB 4
#define ROI 90
#define TT 200
#define HH 3
#define FF 96
#define G3 288
#define NB 12   // BB*HH

typedef unsigned long long u64;

// scratch (device globals; no runtime alloc allowed)
__device__ float g_act[(size_t)NB * ROI * TT * FF];        // (n, roi, t, f)
__device__ float g_xp [(size_t)ROI * TT * NB * G3];        // (roi, t, n, g)

__device__ __forceinline__ u64 pk2(float lo, float hi) {
    u64 r; asm("mov.b64 %0,{%1,%2};" : "=l"(r) : "f"(lo), "f"(hi)); return r;
}
__device__ __forceinline__ void fma2(u64& d, u64 a, u64 b) {
    asm("fma.rn.f32x2 %0,%1,%2,%3;" : "=l"(d) : "l"(a), "l"(b), "l"(d));
}
__device__ __forceinline__ float red2(u64 v) {
    float lo, hi; asm("mov.b64 {%0,%1},%2;" : "=f"(lo), "=f"(hi) : "l"(v));
    return lo + hi;
}
__device__ __forceinline__ float sigmoidf_fast(float x) {
    return __fdividef(1.0f, 1.0f + __expf(-x));
}
__device__ __forceinline__ float tanhf_fast(float x) {
    float e = __expf(2.0f * x);
    return 1.0f - __fdividef(2.0f, e + 1.0f);
}

// ---------------------------------------------------------------------------
// K1: one block per (b,t,h), 576 threads, all 90 rows.
//     W1/W2 staged in smem pre-packed as f32x2 pairs.
// smem layout (floats):
//   wp1   [0, 9216)      48x96 u64
//   wp2   [9216, 18432)  48x96 u64
//   xs    [18432, 27072) 90x96  (x tile, later h1)
//   buf   [27072, 35712) 90x96  (agg)
//   idx8  [35712, 37872) 90x96 bytes
//   cnts  [37872, 37962) 90 ints
// total 151,848 B
// ---------------------------------------------------------------------------
__global__ __launch_bounds__(576, 1) void k1_agg_mlp(
    const float* __restrict__ x, const float* __restrict__ a,
    const float* __restrict__ eps,
    const float* __restrict__ W1, const float* __restrict__ b1,
    const float* __restrict__ g1, const float* __restrict__ be1,
    const float* __restrict__ W2, const float* __restrict__ b2,
    const float* __restrict__ g2, const float* __restrict__ be2)
{
    extern __shared__ float sm[];
    u64*   wp1 = (u64*)sm;                         // [48][96]
    u64*   wp2 = (u64*)(sm + 9216);                // [48][96]
    float* xs  = sm + 18432;                       // [90][96]
    float* buf = sm + 27072;                       // [90][96]
    unsigned char* idx8 = (unsigned char*)(sm + 35712);  // [90][96]
    int* cnts = (int*)(sm + 37872);                // [90]

    const int bid = blockIdx.x;
    const int b   = bid / (TT * HH);
    const int rem = bid % (TT * HH);
    const int t   = rem / HH;
    const int hh  = rem % HH;
    const int tid = threadIdx.x;

    // stage W1/W2 packed: wp[k2][c] = (W[2k2][c], W[2k2+1][c])
    for (int idx = tid; idx < 48 * 96; idx += 576) {
        int k2 = idx / 96, c = idx % 96;
        wp1[idx] = pk2(__ldg(&W1[(2 * k2) * 96 + c]), __ldg(&W1[(2 * k2 + 1) * 96 + c]));
        wp2[idx] = pk2(__ldg(&W2[(2 * k2) * 96 + c]), __ldg(&W2[(2 * k2 + 1) * 96 + c]));
    }

    // load x tile (90x96) as float4
    {
        const float4* xsrc = (const float4*)x;
        for (int idx = tid; idx < ROI * 24; idx += 576) {
            int i = idx / 24, c4 = idx % 24;
            ((float4*)xs)[i * 24 + c4] =
                xsrc[(((((size_t)b * ROI + i) * TT + t) * HH + hh) * FF) / 4 + c4];
        }
    }

    // nonzero index lists (18 warps, 5 rows each)
    const int warp = tid >> 5, lane = tid & 31;
    for (int i = warp; i < ROI; i += 18) {
        size_t aoff = ((((size_t)b * ROI + i) * TT + t) * HH + hh) * ROI;
        int cnt = 0;
        #pragma unroll
        for (int c0 = 0; c0 < 96; c0 += 32) {
            int j = c0 + lane;
            float v = (j < ROI) ? a[aoff + j] : 0.0f;
            unsigned m = __ballot_sync(0xffffffffu, v != 0.0f);
            if (v != 0.0f) {
                int pos = cnt + __popc(m & ((1u << lane) - 1u));
                idx8[i * 96 + pos] = (unsigned char)j;
            }
            cnt += __popc(m);
        }
        if (lane == 0) cnts[i] = cnt;
    }
    __syncthreads();

    const float epsv = eps[0];

    // sparse aggregation (float4 over f) -> buf[90][96]
    {
        const int c4 = tid % 24;
        const int ig = tid / 24;   // 0..23
        for (int i = ig; i < ROI; i += 24) {
            float4 base = ((const float4*)xs)[i * 24 + c4];
            float4 s = make_float4(epsv * base.x, epsv * base.y,
                                   epsv * base.z, epsv * base.w);
            int cnt = cnts[i];
            const unsigned char* il = idx8 + i * 96;
            for (int s0 = 0; s0 < cnt; s0++) {
                int j = il[s0];
                float4 v = ((const float4*)xs)[j * 24 + c4];
                s.x += v.x; s.y += v.y; s.z += v.z; s.w += v.w;
            }
            ((float4*)buf)[i * 24 + c4] = s;
        }
    }
    __syncthreads();

    const int c  = tid % 96;
    const int ib = tid / 96;   // 0..5, rows ib + 6r

    // GEMM1: h1 = elu(bn1(buf @ W1 + b1)) -> xs
    {
        u64 acc[15];
        #pragma unroll
        for (int r = 0; r < 15; r++) acc[r] = 0ull;
        #pragma unroll 4
        for (int k2 = 0; k2 < 48; k2 += 2) {   // 4 k per iter
            u64 w01 = wp1[k2 * 96 + c];
            u64 w23 = wp1[(k2 + 1) * 96 + c];
            #pragma unroll
            for (int r = 0; r < 15; r++) {
                ulonglong2 av = *(const ulonglong2*)&buf[(ib + 6 * r) * 96 + 2 * k2];
                fma2(acc[r], av.x, w01);
                fma2(acc[r], av.y, w23);
            }
        }
        float gs  = g1[c] * rsqrtf(1.0f + 1e-5f);
        float bbv = be1[c];
        float b1c = b1[c];
        __syncthreads();  // x tile dead; safe to overwrite xs
        #pragma unroll
        for (int r = 0; r < 15; r++) {
            int rr = ib + 6 * r;
            float y = (red2(acc[r]) + b1c) * gs + bbv;
            y = (y > 0.0f) ? y : (__expf(y) - 1.0f);
            xs[rr * 96 + c] = y;
        }
    }
    __syncthreads();

    // GEMM2: act = relu(bn2(xs @ W2 + b2))   [relu(elu(v)) == relu(v)]
    {
        u64 acc[15];
        #pragma unroll
        for (int r = 0; r < 15; r++) acc[r] = 0ull;
        #pragma unroll 4
        for (int k2 = 0; k2 < 48; k2 += 2) {
            u64 w01 = wp2[k2 * 96 + c];
            u64 w23 = wp2[(k2 + 1) * 96 + c];
            #pragma unroll
            for (int r = 0; r < 15; r++) {
                ulonglong2 av = *(const ulonglong2*)&xs[(ib + 6 * r) * 96 + 2 * k2];
                fma2(acc[r], av.x, w01);
                fma2(acc[r], av.y, w23);
            }
        }
        float gs  = g2[c] * rsqrtf(1.0f + 1e-5f);
        float bbv = be2[c];
        float b2c = b2[c];
        const int n = b * HH + hh;
        #pragma unroll
        for (int r = 0; r < 15; r++) {
            int i = ib + 6 * r;
            float y = (red2(acc[r]) + b2c) * gs + bbv;
            y = fmaxf(y, 0.0f);
            g_act[(((size_t)n * ROI + i) * TT + t) * FF + c] = y;
        }
    }
}

// ---------------------------------------------------------------------------
// K2 (R3 version): grid (100, 90): 2-t tile -> 24 rows x 288 g x 96 k.
//     288 threads, weights staged in smem, k-chunked.
// ---------------------------------------------------------------------------
#define WPAD 36   // padded chunk row stride (32 k-floats + 4 pad)

__global__ __launch_bounds__(288, 2) void k2_proj(
    const float* __restrict__ Wih, const float* __restrict__ bih)
{
    extern __shared__ float sm[];
    float* acts = sm;                  // 24*96 = 2304 floats
    float* wsm  = sm + 2304;           // 288*36 = 10368 floats

    const int roi = blockIdx.y;
    const int t0  = blockIdx.x * 2;
    const int g   = threadIdx.x;

    {
        const float4* src = (const float4*)g_act;
        for (int idx = g; idx < 24 * 24; idx += 288) {
            int rr = idx / 24, c4 = idx % 24;
            int dt = rr / NB, n = rr % NB;
            ((float4*)acts)[idx] =
                src[((((size_t)n * ROI + roi) * TT + (t0 + dt)) * FF) / 4 + c4];
        }
    }

    u64 acc[24];
    #pragma unroll
    for (int r = 0; r < 24; r++) acc[r] = 0ull;

    const float* wbase = Wih + (size_t)roi * G3 * 96;

    #pragma unroll
    for (int c0 = 0; c0 < 96; c0 += 32) {
        __syncthreads();   // previous chunk consumed (covers acts on first pass)
        #pragma unroll
        for (int it = 0; it < 8; it++) {
            int idx = it * 288 + g;           // 2304 float4 total
            int gg  = idx >> 3;
            int q   = idx & 7;
            float4 w = __ldg((const float4*)(wbase + gg * 96 + c0 + 4 * q));
            *(float4*)&wsm[gg * WPAD + 4 * q] = w;
        }
        __syncthreads();

        const float* wrow = &wsm[g * WPAD];
        #pragma unroll
        for (int kk4 = 0; kk4 < 8; kk4++) {
            ulonglong2 w = *(const ulonglong2*)&wrow[4 * kk4];
            #pragma unroll
            for (int rr = 0; rr < 24; rr++) {
                ulonglong2 av = *(const ulonglong2*)&acts[rr * 96 + c0 + 4 * kk4];
                fma2(acc[rr], av.x, w.x);
                fma2(acc[rr], av.y, w.y);
            }
        }
    }

    const float bv = __ldg(&bih[roi * G3 + g]);
    #pragma unroll
    for (int rr = 0; rr < 24; rr++) {
        int dt = rr / NB, n = rr % NB;
        g_xp[(((size_t)roi * TT + (t0 + dt)) * NB + n) * G3 + g] = red2(acc[rr]) + bv;
    }
}

// ---------------------------------------------------------------------------
// K3 (R3 version): 90 blocks x 576 threads: k-dim split 2-way.
// ---------------------------------------------------------------------------
__global__ __launch_bounds__(576, 1) void k3_gru(
    const float* __restrict__ Whh, const float* __restrict__ bhh,
    float* __restrict__ out)
{
    extern __shared__ float sm[];
    float* hbuf  = sm;            // 12*96  = 1152
    float* rbuf  = sm + 1152;     // 1152
    float* zbuf  = sm + 2304;     // 1152
    float* hpart = sm + 3456;     // 12*288 = 3456

    const int roi = blockIdx.x;
    const int tid = threadIdx.x;
    const int g   = tid % G3;     // gate row
    const int kh  = tid / G3;     // 0: k[0,48)  1: k[48,96)

    u64 wr2[24];
    {
        const ulonglong2* wsrc =
            (const ulonglong2*)(Whh + ((size_t)roi * G3 + g) * 96 + kh * 48);
        #pragma unroll
        for (int kk = 0; kk < 12; kk++) {
            ulonglong2 w = __ldg(&wsrc[kk]);
            wr2[2 * kk + 0] = w.x;
            wr2[2 * kk + 1] = w.y;
        }
    }
    const float bv = __ldg(&bhh[roi * G3 + g]);

    for (int idx = tid; idx < 1152; idx += 576) hbuf[idx] = 0.0f;
    __syncthreads();

    const int gtype = g / 96;   // 0:r  1:z  2:n
    const int j     = g % 96;

    for (int t = 0; t < TT; t++) {
        float xv[NB];
        if (kh == 0) {
            const float* xpb = g_xp + (((size_t)roi * TT + t) * NB) * G3 + g;
            #pragma unroll
            for (int n = 0; n < NB; n++) xv[n] = __ldg(&xpb[n * G3]);
        }

        float hp[NB];
        #pragma unroll
        for (int n = 0; n < NB; n++) {
            u64 a2 = 0ull;
            const ulonglong2* hrow = (const ulonglong2*)&hbuf[n * 96 + kh * 48];
            #pragma unroll
            for (int kk = 0; kk < 12; kk++) {
                ulonglong2 hv = hrow[kk];
                fma2(a2, hv.x, wr2[2 * kk + 0]);
                fma2(a2, hv.y, wr2[2 * kk + 1]);
            }
            hp[n] = red2(a2);
        }
        if (kh == 1) {
            #pragma unroll
            for (int n = 0; n < NB; n++) hpart[n * G3 + g] = hp[n];
        }
        __syncthreads();

        if (kh == 0) {
            #pragma unroll
            for (int n = 0; n < NB; n++) hp[n] += hpart[n * G3 + g] + bv;
            if (gtype < 2) {
                float* dst = (gtype == 0) ? rbuf : zbuf;
                #pragma unroll
                for (int n = 0; n < NB; n++)
                    dst[n * 96 + j] = sigmoidf_fast(xv[n] + hp[n]);
            }
        }
        __syncthreads();

        if (kh == 0 && gtype == 2) {
            #pragma unroll
            for (int n = 0; n < NB; n++) {
                float r  = rbuf[n * 96 + j];
                float z  = zbuf[n * 96 + j];
                float hn = tanhf_fast(xv[n] + r * hp[n]);
                float h0 = hbuf[n * 96 + j];
                float h2 = (1.0f - z) * hn + z * h0;
                hbuf[n * 96 + j] = h2;
                int b  = n / HH, hh = n % HH;
                out[((((size_t)b * ROI + roi) * TT + t) * HH + hh) * 96 + j] = h2;
            }
        }
        __syncthreads();
    }
}

// ---------------------------------------------------------------------------
extern "C" void kernel_launch(void* const* d_in, const int* in_sizes, int n_in,
                              void* d_out, int out_size)
{
    const float* x   = (const float*)d_in[0];
    const float* a   = (const float*)d_in[1];
    const float* eps = (const float*)d_in[2];
    const float* W1  = (const float*)d_in[3];
    const float* b1  = (const float*)d_in[4];
    const float* g1  = (const float*)d_in[5];
    const float* be1 = (const float*)d_in[6];
    const float* W2  = (const float*)d_in[7];
    const float* b2  = (const float*)d_in[8];
    const float* g2  = (const float*)d_in[9];
    const float* be2 = (const float*)d_in[10];
    const float* Wih = (const float*)d_in[11];
    const float* Whh = (const float*)d_in[12];
    const float* bih = (const float*)d_in[13];
    const float* bhh = (const float*)d_in[14];
    float* out = (float*)d_out;

    const int smem1 = 37962 * 4;                              // 151,848 B
    cudaFuncSetAttribute(k1_agg_mlp, cudaFuncAttributeMaxDynamicSharedMemorySize, smem1);

    const int smem2 = (2304 + 288 * WPAD) * 4;                // 50,688 B
    cudaFuncSetAttribute(k2_proj, cudaFuncAttributeMaxDynamicSharedMemorySize, smem2);

    k1_agg_mlp<<<BB * TT * HH, 576, smem1>>>(x, a, eps, W1, b1, g1, be1,
                                             W2, b2, g2, be2);
    k2_proj<<<dim3(TT / 2, ROI), 288, smem2>>>(Wih, bih);
    k3_gru<<<ROI, 576, (1152 * 3 + 3456) * 4>>>(Whh, bhh, out);
}

// round 7
// speedup vs baseline: 1.3532x; 1.1639x over previous
#include <cuda_runtime.h>

#define BB 4
#define ROI 90
#define TT 200
#define HH 3
#define FF 96
#define G3 288
#define NB 12   // BB*HH
#define SEQ_GROUPS 3
#define SEQ_PER 4   // NB / SEQ_GROUPS

typedef unsigned long long u64;

// scratch (device globals; no runtime alloc allowed)
__device__ float g_act[(size_t)NB * ROI * TT * FF];        // (n, roi, t, f)
__device__ float g_xp [(size_t)ROI * TT * NB * G3];        // (roi, t, n, g)

__device__ __forceinline__ u64 pk2(float lo, float hi) {
    u64 r; asm("mov.b64 %0,{%1,%2};" : "=l"(r) : "f"(lo), "f"(hi)); return r;
}
__device__ __forceinline__ void fma2(u64& d, u64 a, u64 b) {
    asm("fma.rn.f32x2 %0,%1,%2,%3;" : "=l"(d) : "l"(a), "l"(b), "l"(d));
}
__device__ __forceinline__ float red2(u64 v) {
    float lo, hi; asm("mov.b64 {%0,%1},%2;" : "=f"(lo), "=f"(hi) : "l"(v));
    return lo + hi;
}
__device__ __forceinline__ float sigmoidf_fast(float x) {
    return __fdividef(1.0f, 1.0f + __expf(-x));
}
__device__ __forceinline__ float tanhf_fast(float x) {
    float e = __expf(2.0f * x);
    return 1.0f - __fdividef(2.0f, e + 1.0f);
}

// ---------------------------------------------------------------------------
// K1 (R3 version): per-(b,t,h, row-half) block
// ---------------------------------------------------------------------------
__global__ __launch_bounds__(288, 2) void k1_agg_mlp(
    const float* __restrict__ x, const float* __restrict__ a,
    const float* __restrict__ eps,
    const float* __restrict__ W1, const float* __restrict__ b1,
    const float* __restrict__ g1, const float* __restrict__ be1,
    const float* __restrict__ W2, const float* __restrict__ b2,
    const float* __restrict__ g2, const float* __restrict__ be2)
{
    extern __shared__ float sm[];
    float* xs  = sm;              // 8640 floats
    float* buf = sm + 8640;       // 4320 floats
    unsigned char* idx8 = (unsigned char*)(sm + 8640 + 4320);  // 45*96 bytes
    int* cnts = (int*)(idx8 + 45 * 96);                        // 45 ints

    const int bid = blockIdx.x;
    const int half = blockIdx.y;
    const int b   = bid / (TT * HH);
    const int rem = bid % (TT * HH);
    const int t   = rem / HH;
    const int hh  = rem % HH;
    const int tid = threadIdx.x;

    {
        const float4* xsrc = (const float4*)x;
        for (int idx = tid; idx < ROI * 24; idx += 288) {
            int i = idx / 24, c4 = idx % 24;
            ((float4*)xs)[i * 24 + c4] =
                xsrc[(((((size_t)b * ROI + i) * TT + t) * HH + hh) * FF) / 4 + c4];
        }
    }

    const int warp = tid >> 5, lane = tid & 31;
    for (int r = warp; r < 45; r += 9) {
        int i = half * 45 + r;
        size_t aoff = ((((size_t)b * ROI + i) * TT + t) * HH + hh) * ROI;
        int cnt = 0;
        #pragma unroll
        for (int c0 = 0; c0 < 96; c0 += 32) {
            int j = c0 + lane;
            float v = (j < ROI) ? a[aoff + j] : 0.0f;
            unsigned m = __ballot_sync(0xffffffffu, v != 0.0f);
            if (v != 0.0f) {
                int pos = cnt + __popc(m & ((1u << lane) - 1u));
                idx8[r * 96 + pos] = (unsigned char)j;
            }
            cnt += __popc(m);
        }
        if (lane == 0) cnts[r] = cnt;
    }
    __syncthreads();

    const float epsv = eps[0];

    {
        const int c4 = tid % 24;
        const int ig = tid / 24;
        for (int r = ig; r < 45; r += 12) {
            int i = half * 45 + r;
            float4 base = ((const float4*)xs)[i * 24 + c4];
            float4 s = make_float4(epsv * base.x, epsv * base.y,
                                   epsv * base.z, epsv * base.w);
            int cnt = cnts[r];
            const unsigned char* il = idx8 + r * 96;
            for (int s0 = 0; s0 < cnt; s0++) {
                int j = il[s0];
                float4 v = ((const float4*)xs)[j * 24 + c4];
                s.x += v.x; s.y += v.y; s.z += v.z; s.w += v.w;
            }
            ((float4*)buf)[r * 24 + c4] = s;
        }
    }
    __syncthreads();

    const int c  = tid % 96;
    const int ib = tid / 96;

    // GEMM1
    {
        u64 acc[15];
        #pragma unroll
        for (int r = 0; r < 15; r++) acc[r] = 0ull;
        for (int k = 0; k < 96; k += 4) {
            float wa = __ldg(&W1[(k + 0) * 96 + c]);
            float wb = __ldg(&W1[(k + 1) * 96 + c]);
            float wc = __ldg(&W1[(k + 2) * 96 + c]);
            float wd = __ldg(&W1[(k + 3) * 96 + c]);
            u64 w01 = pk2(wa, wb), w23 = pk2(wc, wd);
            #pragma unroll
            for (int r = 0; r < 15; r++) {
                ulonglong2 av = *(const ulonglong2*)&buf[(ib + 3 * r) * 96 + k];
                fma2(acc[r], av.x, w01);
                fma2(acc[r], av.y, w23);
            }
        }
        float gs  = g1[c] * rsqrtf(1.0f + 1e-5f);
        float bbv = be1[c];
        float b1c = b1[c];
        __syncthreads();
        #pragma unroll
        for (int r = 0; r < 15; r++) {
            int rr = ib + 3 * r;
            float y = (red2(acc[r]) + b1c) * gs + bbv;
            y = (y > 0.0f) ? y : (__expf(y) - 1.0f);
            xs[rr * 96 + c] = y;
        }
    }
    __syncthreads();

    // GEMM2
    {
        u64 acc[15];
        #pragma unroll
        for (int r = 0; r < 15; r++) acc[r] = 0ull;
        for (int k = 0; k < 96; k += 4) {
            float wa = __ldg(&W2[(k + 0) * 96 + c]);
            float wb = __ldg(&W2[(k + 1) * 96 + c]);
            float wc = __ldg(&W2[(k + 2) * 96 + c]);
            float wd = __ldg(&W2[(k + 3) * 96 + c]);
            u64 w01 = pk2(wa, wb), w23 = pk2(wc, wd);
            #pragma unroll
            for (int r = 0; r < 15; r++) {
                ulonglong2 av = *(const ulonglong2*)&xs[(ib + 3 * r) * 96 + k];
                fma2(acc[r], av.x, w01);
                fma2(acc[r], av.y, w23);
            }
        }
        float gs  = g2[c] * rsqrtf(1.0f + 1e-5f);
        float bbv = be2[c];
        float b2c = b2[c];
        const int n = b * HH + hh;
        #pragma unroll
        for (int r = 0; r < 15; r++) {
            int i = half * 45 + ib + 3 * r;
            float y = (red2(acc[r]) + b2c) * gs + bbv;
            y = fmaxf(y, 0.0f);
            g_act[(((size_t)n * ROI + i) * TT + t) * FF + c] = y;
        }
    }
}

// ---------------------------------------------------------------------------
// K2 (R3 version): grid (100, 90): 2-t tile -> 24 rows x 288 g x 96 k
// ---------------------------------------------------------------------------
#define WPAD 36

__global__ __launch_bounds__(288, 2) void k2_proj(
    const float* __restrict__ Wih, const float* __restrict__ bih)
{
    extern __shared__ float sm[];
    float* acts = sm;                  // 2304 floats
    float* wsm  = sm + 2304;           // 10368 floats

    const int roi = blockIdx.y;
    const int t0  = blockIdx.x * 2;
    const int g   = threadIdx.x;

    {
        const float4* src = (const float4*)g_act;
        for (int idx = g; idx < 24 * 24; idx += 288) {
            int rr = idx / 24, c4 = idx % 24;
            int dt = rr / NB, n = rr % NB;
            ((float4*)acts)[idx] =
                src[((((size_t)n * ROI + roi) * TT + (t0 + dt)) * FF) / 4 + c4];
        }
    }

    u64 acc[24];
    #pragma unroll
    for (int r = 0; r < 24; r++) acc[r] = 0ull;

    const float* wbase = Wih + (size_t)roi * G3 * 96;

    #pragma unroll
    for (int c0 = 0; c0 < 96; c0 += 32) {
        __syncthreads();
        #pragma unroll
        for (int it = 0; it < 8; it++) {
            int idx = it * 288 + g;
            int gg  = idx >> 3;
            int q   = idx & 7;
            float4 w = __ldg((const float4*)(wbase + gg * 96 + c0 + 4 * q));
            *(float4*)&wsm[gg * WPAD + 4 * q] = w;
        }
        __syncthreads();

        const float* wrow = &wsm[g * WPAD];
        #pragma unroll
        for (int kk4 = 0; kk4 < 8; kk4++) {
            ulonglong2 w = *(const ulonglong2*)&wrow[4 * kk4];
            #pragma unroll
            for (int rr = 0; rr < 24; rr++) {
                ulonglong2 av = *(const ulonglong2*)&acts[rr * 96 + c0 + 4 * kk4];
                fma2(acc[rr], av.x, w.x);
                fma2(acc[rr], av.y, w.y);
            }
        }
    }

    const float bv = __ldg(&bih[roi * G3 + g]);
    #pragma unroll
    for (int rr = 0; rr < 24; rr++) {
        int dt = rr / NB, n = rr % NB;
        g_xp[(((size_t)roi * TT + (t0 + dt)) * NB + n) * G3 + g] = red2(acc[rr]) + bv;
    }
}

// ---------------------------------------------------------------------------
// K3: GRU recurrence. grid (90, 3): one block per (roi, 4-seq group).
//     576 threads = 288 gates x 2 k-halves; partials reduced via smem.
// ---------------------------------------------------------------------------
__global__ __launch_bounds__(576, 1) void k3_gru(
    const float* __restrict__ Whh, const float* __restrict__ bhh,
    float* __restrict__ out)
{
    __shared__ __align__(16) float hbuf[SEQ_PER * 96];    // 4x96
    __shared__ __align__(16) float rbuf[SEQ_PER * 96];
    __shared__ __align__(16) float zbuf[SEQ_PER * 96];
    __shared__ __align__(16) float hpart[SEQ_PER * G3];   // 4x288

    const int roi = blockIdx.x;
    const int sg  = blockIdx.y;          // seq group: seqs [4sg, 4sg+4)
    const int tid = threadIdx.x;
    const int g   = tid % G3;
    const int kh  = tid / G3;            // 0: k[0,48)  1: k[48,96)

    u64 wr2[24];
    {
        const ulonglong2* wsrc =
            (const ulonglong2*)(Whh + ((size_t)roi * G3 + g) * 96 + kh * 48);
        #pragma unroll
        for (int kk = 0; kk < 12; kk++) {
            ulonglong2 w = __ldg(&wsrc[kk]);
            wr2[2 * kk + 0] = w.x;
            wr2[2 * kk + 1] = w.y;
        }
    }
    const float bv = __ldg(&bhh[roi * G3 + g]);

    for (int idx = tid; idx < SEQ_PER * 96; idx += 576) hbuf[idx] = 0.0f;
    __syncthreads();

    const int gtype = g / 96;   // 0:r  1:z  2:n
    const int j     = g % 96;

    for (int t = 0; t < TT; t++) {
        // this step's xp for the 4 sequences (lower half only)
        float xv[SEQ_PER];
        if (kh == 0) {
            const float* xpb =
                g_xp + ((((size_t)roi * TT + t) * NB) + sg * SEQ_PER) * G3 + g;
            #pragma unroll
            for (int n = 0; n < SEQ_PER; n++) xv[n] = __ldg(&xpb[n * G3]);
        }

        // partial dot products over this half's k range
        float hp[SEQ_PER];
        #pragma unroll
        for (int n = 0; n < SEQ_PER; n++) {
            u64 a2 = 0ull;
            const ulonglong2* hrow = (const ulonglong2*)&hbuf[n * 96 + kh * 48];
            #pragma unroll
            for (int kk = 0; kk < 12; kk++) {
                ulonglong2 hv = hrow[kk];
                fma2(a2, hv.x, wr2[2 * kk + 0]);
                fma2(a2, hv.y, wr2[2 * kk + 1]);
            }
            hp[n] = red2(a2);
        }
        if (kh == 1) {
            #pragma unroll
            for (int n = 0; n < SEQ_PER; n++) hpart[n * G3 + g] = hp[n];
        }
        __syncthreads();

        if (kh == 0) {
            #pragma unroll
            for (int n = 0; n < SEQ_PER; n++) hp[n] += hpart[n * G3 + g] + bv;
            if (gtype < 2) {
                float* dst = (gtype == 0) ? rbuf : zbuf;
                #pragma unroll
                for (int n = 0; n < SEQ_PER; n++)
                    dst[n * 96 + j] = sigmoidf_fast(xv[n] + hp[n]);
            }
        }
        __syncthreads();

        if (kh == 0 && gtype == 2) {
            #pragma unroll
            for (int n = 0; n < SEQ_PER; n++) {
                float r  = rbuf[n * 96 + j];
                float z  = zbuf[n * 96 + j];
                float hn = tanhf_fast(xv[n] + r * hp[n]);
                float h0 = hbuf[n * 96 + j];
                float h2 = (1.0f - z) * hn + z * h0;
                hbuf[n * 96 + j] = h2;
                int nn = sg * SEQ_PER + n;
                int b  = nn / HH, hh = nn % HH;
                out[((((size_t)b * ROI + roi) * TT + t) * HH + hh) * 96 + j] = h2;
            }
        }
        __syncthreads();
    }
}

// ---------------------------------------------------------------------------
extern "C" void kernel_launch(void* const* d_in, const int* in_sizes, int n_in,
                              void* d_out, int out_size)
{
    const float* x   = (const float*)d_in[0];
    const float* a   = (const float*)d_in[1];
    const float* eps = (const float*)d_in[2];
    const float* W1  = (const float*)d_in[3];
    const float* b1  = (const float*)d_in[4];
    const float* g1  = (const float*)d_in[5];
    const float* be1 = (const float*)d_in[6];
    const float* W2  = (const float*)d_in[7];
    const float* b2  = (const float*)d_in[8];
    const float* g2  = (const float*)d_in[9];
    const float* be2 = (const float*)d_in[10];
    const float* Wih = (const float*)d_in[11];
    const float* Whh = (const float*)d_in[12];
    const float* bih = (const float*)d_in[13];
    const float* bhh = (const float*)d_in[14];
    float* out = (float*)d_out;

    const int smem1 = (8640 + 4320) * 4 + 45 * 96 + 45 * 4;   // 56,340 B
    cudaFuncSetAttribute(k1_agg_mlp, cudaFuncAttributeMaxDynamicSharedMemorySize, smem1);

    const int smem2 = (2304 + 288 * WPAD) * 4;                // 50,688 B
    cudaFuncSetAttribute(k2_proj, cudaFuncAttributeMaxDynamicSharedMemorySize, smem2);

    k1_agg_mlp<<<dim3(BB * TT * HH, 2), 288, smem1>>>(x, a, eps, W1, b1, g1, be1,
                                                      W2, b2, g2, be2);
    k2_proj<<<dim3(TT / 2, ROI), 288, smem2>>>(Wih, bih);
    k3_gru<<<dim3(ROI, SEQ_GROUPS), 576>>>(Whh, bhh, out);
}